// round 8
// baseline (speedup 1.0000x reference)
#include <cuda_runtime.h>
#include <math.h>

// Problem constants (fixed shapes from reference)
#define BB   16      // batch
#define SS   128     // steps / nodes
#define TT   160     // sentence length
#define HH   512     // hidden
#define EE   512     // embed
#define RDIM 128     // relation embed dim
#define VV   32000   // vocab

// -------- device scratch (no allocations allowed) --------
__device__ __align__(16) float g_h[2][2][BB][HH];   // [parity][layer][b][k]
__device__ __align__(16) float g_c[2][2][BB][HH];
__device__ unsigned long long g_amax[SS][BB];       // encoded (value, index) per step
__device__ int g_mask_is_byte;

// -------- packed fp32x2 FMA (Blackwell) --------
static __device__ __forceinline__ unsigned long long ffma2(unsigned long long a,
                                                           unsigned long long b,
                                                           unsigned long long c) {
    unsigned long long d;
    asm("fma.rn.f32x2 %0, %1, %2, %3;" : "=l"(d) : "l"(a), "l"(b), "l"(c));
    return d;
}
static __device__ __forceinline__ float2 upk(unsigned long long v) {
    float2 r;
    asm("mov.b64 {%0, %1}, %2;" : "=f"(r.x), "=f"(r.y) : "l"(v));
    return r;
}
static __device__ __forceinline__ float wsum(float s) {
#pragma unroll
    for (int o = 16; o; o >>= 1) s += __shfl_xor_sync(0xffffffffu, s, o);
    return s;
}
static __device__ __forceinline__ double sigd(double x) { return 1.0 / (1.0 + exp(-x)); }

// ---------------------------------------------------------------------------
// init: zero argmax slots, tile hiddens into (h,c) for both layers (parity 0),
// and detect whether teacher_mask arrived as 1-byte bool or int32.
// ---------------------------------------------------------------------------
__global__ void init_kernel(const float* __restrict__ hiddens,
                            const unsigned char* __restrict__ tmask) {
    int tid = threadIdx.x;
    for (int i = tid; i < SS * BB; i += blockDim.x)
        ((unsigned long long*)g_amax)[i] = 0ull;
    float* hf = &g_h[0][0][0][0];
    float* cf = &g_c[0][0][0][0];
    for (int i = tid; i < BB * HH; i += blockDim.x) {
        float v = hiddens[i];
        hf[i] = v; hf[BB * HH + i] = v;
        cf[i] = v; cf[BB * HH + i] = v;
    }
    __shared__ int sflag;
    if (tid == 0) sflag = 0;
    __syncthreads();
    // int32 little-endian 0/1 => bytes at i%4!=0 are all zero.
    // bool8 => those byte positions carry real 0/1 mask values (~half ones).
    int f = 0;
    for (int i = tid; i < BB * SS; i += blockDim.x)
        if ((i & 3) && tmask[i]) f = 1;
    if (f) atomicOr(&sflag, 1);
    __syncthreads();
    if (tid == 0) g_mask_is_byte = sflag;
}

// ---------------------------------------------------------------------------
// LSTM layer 0: one warp per (b, cell j). Input x = [rel_emb[rel], word(640)],
// word chosen from teacher (gold) / previous argmax / SOS at t==0.
// ---------------------------------------------------------------------------
__global__ void lstm0_kernel(int t,
                             const float* __restrict__ w_ih,
                             const float* __restrict__ w_hh,
                             const float* __restrict__ bias,
                             const float* __restrict__ rel_emb,
                             const float* __restrict__ embed,
                             const int* __restrict__ relations,
                             const int* __restrict__ gold,
                             const unsigned char* __restrict__ tmask) {
    int gw = blockIdx.x * (blockDim.x >> 5) + (threadIdx.x >> 5);
    int lane = threadIdx.x & 31;
    int b = gw >> 9;
    int j = gw & 511;
    int p = t & 1;

    int widx;
    if (t == 0) {
        widx = 1;  // SOS / null token
    } else {
        int m;
        if (g_mask_is_byte) m = tmask[b * SS + t];
        else                m = ((const int*)tmask)[b * SS + t];
        if (m) widx = gold[b * SS + t - 1];
        else   widx = (int)(0xFFFFFFFFu - (unsigned)(g_amax[t - 1][b] & 0xFFFFFFFFull));
    }
    int rel = relations[b * SS + t];

    typedef ulonglong2 u2;
    const u2* rp = (const u2*)(rel_emb + (long)rel * RDIM);
    const u2* wp = (const u2*)(embed + (long)widx * EE);
    const u2* hp = (const u2*)(&g_h[p][0][b][0]);
    u2 xr = rp[lane];
    u2 xw[4], xh[4];
#pragma unroll
    for (int i = 0; i < 4; i++) xw[i] = wp[lane + 32 * i];
#pragma unroll
    for (int i = 0; i < 4; i++) xh[i] = hp[lane + 32 * i];

    float gate[4];
#pragma unroll
    for (int gi = 0; gi < 4; gi++) {
        int r = j + gi * 512;
        const u2* wi = (const u2*)(w_ih + (long)r * (RDIM + EE));
        const u2* wh = (const u2*)(w_hh + (long)r * HH);
        unsigned long long a0 = 0ull, a1 = 0ull;
        u2 w0 = wi[lane];
        a0 = ffma2(w0.x, xr.x, a0); a1 = ffma2(w0.y, xr.y, a1);
#pragma unroll
        for (int i = 0; i < 4; i++) {
            u2 w = wi[32 + lane + 32 * i];
            a0 = ffma2(w.x, xw[i].x, a0); a1 = ffma2(w.y, xw[i].y, a1);
        }
#pragma unroll
        for (int i = 0; i < 4; i++) {
            u2 w = wh[lane + 32 * i];
            a0 = ffma2(w.x, xh[i].x, a0); a1 = ffma2(w.y, xh[i].y, a1);
        }
        float2 f0 = upk(a0), f1 = upk(a1);
        gate[gi] = wsum((f0.x + f0.y) + (f1.x + f1.y)) + bias[r];
    }
    if (lane == 0) {
        // double-precision nonlinearities: fast-math-proof, ~correctly rounded
        double i_ = sigd((double)gate[0]);
        double f_ = sigd((double)gate[1]);
        double g_ = tanh((double)gate[2]);
        double o_ = sigd((double)gate[3]);
        float cold = g_c[p][0][b][j];
        float cnew = (float)(f_ * (double)cold + i_ * g_);
        float hnew = (float)(o_ * tanh((double)cnew));
        g_c[p ^ 1][0][b][j] = cnew;
        g_h[p ^ 1][0][b][j] = hnew;
    }
}

// ---------------------------------------------------------------------------
// LSTM layer 1: input = layer0's fresh h (parity p^1), state = layer1 (parity p).
// ---------------------------------------------------------------------------
__global__ void lstm1_kernel(int t,
                             const float* __restrict__ w_ih,
                             const float* __restrict__ w_hh,
                             const float* __restrict__ bias) {
    int gw = blockIdx.x * (blockDim.x >> 5) + (threadIdx.x >> 5);
    int lane = threadIdx.x & 31;
    int b = gw >> 9;
    int j = gw & 511;
    int p = t & 1;

    typedef ulonglong2 u2;
    const u2* xp = (const u2*)(&g_h[p ^ 1][0][b][0]);
    const u2* hp = (const u2*)(&g_h[p][1][b][0]);
    u2 xx[4], xh[4];
#pragma unroll
    for (int i = 0; i < 4; i++) xx[i] = xp[lane + 32 * i];
#pragma unroll
    for (int i = 0; i < 4; i++) xh[i] = hp[lane + 32 * i];

    float gate[4];
#pragma unroll
    for (int gi = 0; gi < 4; gi++) {
        int r = j + gi * 512;
        const u2* wi = (const u2*)(w_ih + (long)r * HH);
        const u2* wh = (const u2*)(w_hh + (long)r * HH);
        unsigned long long a0 = 0ull, a1 = 0ull;
#pragma unroll
        for (int i = 0; i < 4; i++) {
            u2 w = wi[lane + 32 * i];
            a0 = ffma2(w.x, xx[i].x, a0); a1 = ffma2(w.y, xx[i].y, a1);
        }
#pragma unroll
        for (int i = 0; i < 4; i++) {
            u2 w = wh[lane + 32 * i];
            a0 = ffma2(w.x, xh[i].x, a0); a1 = ffma2(w.y, xh[i].y, a1);
        }
        float2 f0 = upk(a0), f1 = upk(a1);
        gate[gi] = wsum((f0.x + f0.y) + (f1.x + f1.y)) + bias[r];
    }
    if (lane == 0) {
        double i_ = sigd((double)gate[0]);
        double f_ = sigd((double)gate[1]);
        double g_ = tanh((double)gate[2]);
        double o_ = sigd((double)gate[3]);
        float cold = g_c[p][1][b][j];
        float cnew = (float)(f_ * (double)cold + i_ * g_);
        float hnew = (float)(o_ * tanh((double)cnew));
        g_c[p ^ 1][1][b][j] = cnew;
        g_h[p ^ 1][1][b][j] = hnew;
    }
}

// ---------------------------------------------------------------------------
// Vocab projection + argmax. grid = 16 batches * 125 row-blocks; each warp
// computes 32 rows (512-length dots, fp32x2 FMA, warp-butterfly reduce).
// Key encoding: (orderable float << 32) | (0xFFFFFFFF - index) so atomicMax
// picks max value, lowest index on ties (matches jnp.argmax).
// ---------------------------------------------------------------------------
__global__ void outproj_kernel(int t,
                               const float* __restrict__ out_w,
                               const float* __restrict__ out_b) {
    int b  = blockIdx.x / 125;
    int rb = blockIdx.x % 125;
    int warp = threadIdx.x >> 5, lane = threadIdx.x & 31;

    typedef ulonglong2 u2;
    const u2* hp = (const u2*)(&g_h[(t + 1) & 1][1][b][0]);
    u2 h[4];
#pragma unroll
    for (int i = 0; i < 4; i++) h[i] = hp[lane + 32 * i];

    int v0 = rb * 256 + warp * 32;
    float bestv = -1e30f;
    int besti = v0;
#pragma unroll 2
    for (int r = 0; r < 32; r++) {
        int v = v0 + r;
        const u2* wp = (const u2*)(out_w + (long)v * HH);
        unsigned long long a0 = 0ull, a1 = 0ull;
#pragma unroll
        for (int i = 0; i < 4; i++) {
            u2 w = wp[lane + 32 * i];
            a0 = ffma2(w.x, h[i].x, a0); a1 = ffma2(w.y, h[i].y, a1);
        }
        float2 f0 = upk(a0), f1 = upk(a1);
        float s = wsum((f0.x + f0.y) + (f1.x + f1.y)) + out_b[v];
        if (s > bestv) { bestv = s; besti = v; }  // strict > keeps first index on ties
    }
    unsigned u = __float_as_uint(bestv);
    u = (u & 0x80000000u) ? ~u : (u | 0x80000000u);
    unsigned long long key =
        ((unsigned long long)u << 32) |
        (unsigned long long)(0xFFFFFFFFu - (unsigned)besti);

    __shared__ unsigned long long sk[8];
    if (lane == 0) sk[warp] = key;
    __syncthreads();
    if (threadIdx.x == 0) {
        unsigned long long m = sk[0];
#pragma unroll
        for (int i = 1; i < 8; i++) if (sk[i] > m) m = sk[i];
        atomicMax(&g_amax[t][b], m);
    }
}

// ---------------------------------------------------------------------------
// finalize: out[b,t,:] = transfer_w[argmax] for t<128, else sentences[b,t,:].
// (soft + stopgrad(hard - soft) == hard up to ~1e-9 relative rounding.)
// ---------------------------------------------------------------------------
__global__ void finalize_kernel(const float* __restrict__ sentences,
                                const float* __restrict__ transfer_w,
                                float* __restrict__ out) {
    int bt = blockIdx.x;
    int b = bt / TT;
    int t = bt - b * TT;
    const float4* src;
    if (t < SS) {
        int idx = (int)(0xFFFFFFFFu - (unsigned)(g_amax[t][b] & 0xFFFFFFFFull));
        src = (const float4*)(transfer_w + (long)idx * EE);
    } else {
        src = (const float4*)(sentences + (long)bt * EE);
    }
    ((float4*)(out + (long)bt * EE))[threadIdx.x] = src[threadIdx.x];
}

// ---------------------------------------------------------------------------
extern "C" void kernel_launch(void* const* d_in, const int* in_sizes, int n_in,
                              void* d_out, int out_size) {
    const float* hiddens    = (const float*)d_in[0];
    const float* sentences  = (const float*)d_in[1];
    const int*   relations  = (const int*)d_in[2];
    const int*   gold       = (const int*)d_in[3];
    const unsigned char* tmask = (const unsigned char*)d_in[4];
    const float* embed      = (const float*)d_in[5];
    const float* rel_emb    = (const float*)d_in[6];
    const float* w_ih0      = (const float*)d_in[7];
    const float* w_hh0      = (const float*)d_in[8];
    const float* b0         = (const float*)d_in[9];
    const float* w_ih1      = (const float*)d_in[10];
    const float* w_hh1      = (const float*)d_in[11];
    const float* b1         = (const float*)d_in[12];
    const float* out_w      = (const float*)d_in[13];
    const float* out_b      = (const float*)d_in[14];
    const float* transfer_w = (const float*)d_in[15];

    init_kernel<<<1, 1024>>>(hiddens, tmask);
    for (int t = 0; t < SS; t++) {
        lstm0_kernel<<<1024, 256>>>(t, w_ih0, w_hh0, b0, rel_emb, embed,
                                    relations, gold, tmask);
        lstm1_kernel<<<1024, 256>>>(t, w_ih1, w_hh1, b1);
        outproj_kernel<<<2000, 256>>>(t, out_w, out_b);
    }
    finalize_kernel<<<BB * TT, 128>>>(sentences, transfer_w, (float*)d_out);
}

// round 9
// speedup vs baseline: 1.5419x; 1.5419x over previous
#include <cuda_runtime.h>
#include <math.h>

// Problem constants (fixed shapes from reference)
#define BB   16      // batch
#define SS   128     // steps / nodes
#define TT   160     // sentence length
#define HH   512     // hidden
#define EE   512     // embed
#define RDIM 128     // relation embed dim
#define VV   32000   // vocab

// -------- device scratch (no allocations allowed) --------
__device__ __align__(16) float g_h[2][2][BB][HH];   // [parity][layer][b][k]
__device__ __align__(16) float g_c[2][2][BB][HH];
__device__ unsigned long long g_amax[SS][BB];       // encoded (value, index) per step
__device__ int g_mask_is_byte;

// -------- packed fp32x2 FMA (Blackwell) --------
static __device__ __forceinline__ unsigned long long ffma2(unsigned long long a,
                                                           unsigned long long b,
                                                           unsigned long long c) {
    unsigned long long d;
    asm("fma.rn.f32x2 %0, %1, %2, %3;" : "=l"(d) : "l"(a), "l"(b), "l"(c));
    return d;
}
static __device__ __forceinline__ float2 upk(unsigned long long v) {
    float2 r;
    asm("mov.b64 {%0, %1}, %2;" : "=f"(r.x), "=f"(r.y) : "l"(v));
    return r;
}
static __device__ __forceinline__ float wsum(float s) {
#pragma unroll
    for (int o = 16; o; o >>= 1) s += __shfl_xor_sync(0xffffffffu, s, o);
    return s;
}
static __device__ __forceinline__ double sigd(double x) { return 1.0 / (1.0 + exp(-x)); }

// ---------------------------------------------------------------------------
// init: zero argmax slots, tile hiddens into (h,c) for both layers (parity 0),
// and detect whether teacher_mask arrived as 1-byte bool or int32.
// ---------------------------------------------------------------------------
__global__ void init_kernel(const float* __restrict__ hiddens,
                            const unsigned char* __restrict__ tmask) {
    int tid = threadIdx.x;
    for (int i = tid; i < SS * BB; i += blockDim.x)
        ((unsigned long long*)g_amax)[i] = 0ull;
    float* hf = &g_h[0][0][0][0];
    float* cf = &g_c[0][0][0][0];
    for (int i = tid; i < BB * HH; i += blockDim.x) {
        float v = hiddens[i];
        hf[i] = v; hf[BB * HH + i] = v;
        cf[i] = v; cf[BB * HH + i] = v;
    }
    __shared__ int sflag;
    if (tid == 0) sflag = 0;
    __syncthreads();
    // int32 little-endian 0/1 => bytes at i%4!=0 are all zero.
    // bool8 => those byte positions carry real 0/1 mask values (~half ones).
    int f = 0;
    for (int i = tid; i < BB * SS; i += blockDim.x)
        if ((i & 3) && tmask[i]) f = 1;
    if (f) atomicOr(&sflag, 1);
    __syncthreads();
    if (tid == 0) g_mask_is_byte = sflag;
}

// ---------------------------------------------------------------------------
// LSTM layer 0: one warp per (b, cell j). Input x = [rel_emb[rel], word(640)],
// word chosen from teacher (gold) / previous argmax / SOS at t==0.
// ---------------------------------------------------------------------------
__global__ void lstm0_kernel(int t,
                             const float* __restrict__ w_ih,
                             const float* __restrict__ w_hh,
                             const float* __restrict__ bias,
                             const float* __restrict__ rel_emb,
                             const float* __restrict__ embed,
                             const int* __restrict__ relations,
                             const int* __restrict__ gold,
                             const unsigned char* __restrict__ tmask) {
    int gw = blockIdx.x * (blockDim.x >> 5) + (threadIdx.x >> 5);
    int lane = threadIdx.x & 31;
    int b = gw >> 9;
    int j = gw & 511;
    int p = t & 1;

    int widx;
    if (t == 0) {
        widx = 1;  // SOS / null token
    } else {
        int m;
        if (g_mask_is_byte) m = tmask[b * SS + t];
        else                m = ((const int*)tmask)[b * SS + t];
        if (m) widx = gold[b * SS + t - 1];
        else   widx = (int)(0xFFFFFFFFu - (unsigned)(g_amax[t - 1][b] & 0xFFFFFFFFull));
    }
    int rel = relations[b * SS + t];

    typedef ulonglong2 u2;
    const u2* rp = (const u2*)(rel_emb + (long)rel * RDIM);
    const u2* wp = (const u2*)(embed + (long)widx * EE);
    const u2* hp = (const u2*)(&g_h[p][0][b][0]);
    u2 xr = rp[lane];
    u2 xw[4], xh[4];
#pragma unroll
    for (int i = 0; i < 4; i++) xw[i] = wp[lane + 32 * i];
#pragma unroll
    for (int i = 0; i < 4; i++) xh[i] = hp[lane + 32 * i];

    float gate[4];
#pragma unroll
    for (int gi = 0; gi < 4; gi++) {
        int r = j + gi * 512;
        const u2* wi = (const u2*)(w_ih + (long)r * (RDIM + EE));
        const u2* wh = (const u2*)(w_hh + (long)r * HH);
        unsigned long long a0 = 0ull, a1 = 0ull;
        u2 w0 = wi[lane];
        a0 = ffma2(w0.x, xr.x, a0); a1 = ffma2(w0.y, xr.y, a1);
#pragma unroll
        for (int i = 0; i < 4; i++) {
            u2 w = wi[32 + lane + 32 * i];
            a0 = ffma2(w.x, xw[i].x, a0); a1 = ffma2(w.y, xw[i].y, a1);
        }
#pragma unroll
        for (int i = 0; i < 4; i++) {
            u2 w = wh[lane + 32 * i];
            a0 = ffma2(w.x, xh[i].x, a0); a1 = ffma2(w.y, xh[i].y, a1);
        }
        float2 f0 = upk(a0), f1 = upk(a1);
        gate[gi] = wsum((f0.x + f0.y) + (f1.x + f1.y)) + bias[r];
    }
    if (lane == 0) {
        // double-precision nonlinearities: fast-math-proof, ~correctly rounded
        double i_ = sigd((double)gate[0]);
        double f_ = sigd((double)gate[1]);
        double g_ = tanh((double)gate[2]);
        double o_ = sigd((double)gate[3]);
        float cold = g_c[p][0][b][j];
        float cnew = (float)(f_ * (double)cold + i_ * g_);
        float hnew = (float)(o_ * tanh((double)cnew));
        g_c[p ^ 1][0][b][j] = cnew;
        g_h[p ^ 1][0][b][j] = hnew;
    }
}

// ---------------------------------------------------------------------------
// LSTM layer 1: input = layer0's fresh h (parity p^1), state = layer1 (parity p).
// ---------------------------------------------------------------------------
__global__ void lstm1_kernel(int t,
                             const float* __restrict__ w_ih,
                             const float* __restrict__ w_hh,
                             const float* __restrict__ bias) {
    int gw = blockIdx.x * (blockDim.x >> 5) + (threadIdx.x >> 5);
    int lane = threadIdx.x & 31;
    int b = gw >> 9;
    int j = gw & 511;
    int p = t & 1;

    typedef ulonglong2 u2;
    const u2* xp = (const u2*)(&g_h[p ^ 1][0][b][0]);
    const u2* hp = (const u2*)(&g_h[p][1][b][0]);
    u2 xx[4], xh[4];
#pragma unroll
    for (int i = 0; i < 4; i++) xx[i] = xp[lane + 32 * i];
#pragma unroll
    for (int i = 0; i < 4; i++) xh[i] = hp[lane + 32 * i];

    float gate[4];
#pragma unroll
    for (int gi = 0; gi < 4; gi++) {
        int r = j + gi * 512;
        const u2* wi = (const u2*)(w_ih + (long)r * HH);
        const u2* wh = (const u2*)(w_hh + (long)r * HH);
        unsigned long long a0 = 0ull, a1 = 0ull;
#pragma unroll
        for (int i = 0; i < 4; i++) {
            u2 w = wi[lane + 32 * i];
            a0 = ffma2(w.x, xx[i].x, a0); a1 = ffma2(w.y, xx[i].y, a1);
        }
#pragma unroll
        for (int i = 0; i < 4; i++) {
            u2 w = wh[lane + 32 * i];
            a0 = ffma2(w.x, xh[i].x, a0); a1 = ffma2(w.y, xh[i].y, a1);
        }
        float2 f0 = upk(a0), f1 = upk(a1);
        gate[gi] = wsum((f0.x + f0.y) + (f1.x + f1.y)) + bias[r];
    }
    if (lane == 0) {
        double i_ = sigd((double)gate[0]);
        double f_ = sigd((double)gate[1]);
        double g_ = tanh((double)gate[2]);
        double o_ = sigd((double)gate[3]);
        float cold = g_c[p][1][b][j];
        float cnew = (float)(f_ * (double)cold + i_ * g_);
        float hnew = (float)(o_ * tanh((double)cnew));
        g_c[p ^ 1][1][b][j] = cnew;
        g_h[p ^ 1][1][b][j] = hnew;
    }
}

// ---------------------------------------------------------------------------
// Vocab projection + argmax. grid = 16 batches * 125 row-blocks; each warp
// computes 32 rows (512-length dots, fp32x2 FMA, warp-butterfly reduce).
// Key encoding: (orderable float << 32) | (0xFFFFFFFF - index) so atomicMax
// picks max value, lowest index on ties (matches jnp.argmax).
// ---------------------------------------------------------------------------
__global__ void outproj_kernel(int t,
                               const float* __restrict__ out_w,
                               const float* __restrict__ out_b) {
    int b  = blockIdx.x / 125;
    int rb = blockIdx.x % 125;
    int warp = threadIdx.x >> 5, lane = threadIdx.x & 31;

    typedef ulonglong2 u2;
    const u2* hp = (const u2*)(&g_h[(t + 1) & 1][1][b][0]);
    u2 h[4];
#pragma unroll
    for (int i = 0; i < 4; i++) h[i] = hp[lane + 32 * i];

    int v0 = rb * 256 + warp * 32;
    float bestv = -1e30f;
    int besti = v0;
#pragma unroll 2
    for (int r = 0; r < 32; r++) {
        int v = v0 + r;
        const u2* wp = (const u2*)(out_w + (long)v * HH);
        unsigned long long a0 = 0ull, a1 = 0ull;
#pragma unroll
        for (int i = 0; i < 4; i++) {
            u2 w = wp[lane + 32 * i];
            a0 = ffma2(w.x, h[i].x, a0); a1 = ffma2(w.y, h[i].y, a1);
        }
        float2 f0 = upk(a0), f1 = upk(a1);
        float s = wsum((f0.x + f0.y) + (f1.x + f1.y)) + out_b[v];
        if (s > bestv) { bestv = s; besti = v; }  // strict > keeps first index on ties
    }
    unsigned u = __float_as_uint(bestv);
    u = (u & 0x80000000u) ? ~u : (u | 0x80000000u);
    unsigned long long key =
        ((unsigned long long)u << 32) |
        (unsigned long long)(0xFFFFFFFFu - (unsigned)besti);

    __shared__ unsigned long long sk[8];
    if (lane == 0) sk[warp] = key;
    __syncthreads();
    if (threadIdx.x == 0) {
        unsigned long long m = sk[0];
#pragma unroll
        for (int i = 1; i < 8; i++) if (sk[i] > m) m = sk[i];
        atomicMax(&g_amax[t][b], m);
    }
}

// ---------------------------------------------------------------------------
// finalize: out[b,t,:] = transfer_w[argmax] for t<128, else sentences[b,t,:].
// (soft + stopgrad(hard - soft) == hard up to ~1e-9 relative rounding.)
// ---------------------------------------------------------------------------
__global__ void finalize_kernel(const float* __restrict__ sentences,
                                const float* __restrict__ transfer_w,
                                float* __restrict__ out) {
    int bt = blockIdx.x;
    int b = bt / TT;
    int t = bt - b * TT;
    const float4* src;
    if (t < SS) {
        int idx = (int)(0xFFFFFFFFu - (unsigned)(g_amax[t][b] & 0xFFFFFFFFull));
        src = (const float4*)(transfer_w + (long)idx * EE);
    } else {
        src = (const float4*)(sentences + (long)bt * EE);
    }
    ((float4*)(out + (long)bt * EE))[threadIdx.x] = src[threadIdx.x];
}

// ---------------------------------------------------------------------------
extern "C" void kernel_launch(void* const* d_in, const int* in_sizes, int n_in,
                              void* d_out, int out_size) {
    const float* hiddens    = (const float*)d_in[0];
    const float* sentences  = (const float*)d_in[1];
    const int*   relations  = (const int*)d_in[2];
    const int*   gold       = (const int*)d_in[3];
    const unsigned char* tmask = (const unsigned char*)d_in[4];
    const float* embed      = (const float*)d_in[5];
    const float* rel_emb    = (const float*)d_in[6];
    const float* w_ih0      = (const float*)d_in[7];
    const float* w_hh0      = (const float*)d_in[8];
    const float* b0         = (const float*)d_in[9];
    const float* w_ih1      = (const float*)d_in[10];
    const float* w_hh1      = (const float*)d_in[11];
    const float* b1         = (const float*)d_in[12];
    const float* out_w      = (const float*)d_in[13];
    const float* out_b      = (const float*)d_in[14];
    const float* transfer_w = (const float*)d_in[15];

    init_kernel<<<1, 1024>>>(hiddens, tmask);
    for (int t = 0; t < SS; t++) {
        lstm0_kernel<<<1024, 256>>>(t, w_ih0, w_hh0, b0, rel_emb, embed,
                                    relations, gold, tmask);
        lstm1_kernel<<<1024, 256>>>(t, w_ih1, w_hh1, b1);
        outproj_kernel<<<2000, 256>>>(t, out_w, out_b);
    }
    finalize_kernel<<<BB * TT, 128>>>(sentences, transfer_w, (float*)d_out);
}